// round 10
// baseline (speedup 1.0000x reference)
#include <cuda_runtime.h>
#include <math.h>

#define NMAX 100352
#define EMAX 1605632
#define BN_EPS 1e-3f

__device__ float g_emb [NMAX * 32];
__device__ float g_u   [NMAX * 32];
__device__ float g_v   [NMAX * 32];
__device__ float g_sums[128];      // [0:32) s1, [32:64) q1, [64:96) s2, [96:128) q2

__device__ int   g_deg [NMAX];
__device__ int   g_off [NMAX];
__device__ int   g_cur [NMAX];
__device__ int   g_btot[592];
__device__ int   g_csr [EMAX];

__device__ unsigned g_bar_count = 0;
__device__ unsigned g_bar_gen   = 0;

typedef unsigned long long u64;

__device__ __forceinline__ u64 pack2(float x, float y) {
    u64 r; asm("mov.b64 %0, {%1, %2};" : "=l"(r) : "f"(x), "f"(y)); return r;
}
__device__ __forceinline__ void unpack2(u64 v, float& x, float& y) {
    asm("mov.b64 {%0, %1}, %2;" : "=f"(x), "=f"(y) : "l"(v));
}
__device__ __forceinline__ u64 ffma2(u64 a, u64 b, u64 c) {
    u64 d; asm("fma.rn.f32x2 %0, %1, %2, %3;" : "=l"(d) : "l"(a), "l"(b), "l"(c)); return d;
}
__device__ __forceinline__ u64 add2(u64 a, u64 b) {
    u64 d; asm("add.rn.f32x2 %0, %1, %2;" : "=l"(d) : "l"(a), "l"(b)); return d;
}
__device__ __forceinline__ float eluf(float x) { return x > 0.f ? x : expm1f(x); }

__global__ void k_zero(int N) {
    int i = blockIdx.x * blockDim.x + threadIdx.x;
    if (i < 128) g_sums[i] = 0.f;
    for (int n = i; n < N; n += gridDim.x * blockDim.x) g_deg[n] = 0;
}

// all blocks must be resident (grid == guaranteed-resident capacity)
__device__ __forceinline__ void grid_barrier() {
    __syncthreads();
    if (threadIdx.x == 0) {
        __threadfence();
        unsigned gen = *(volatile unsigned*)&g_bar_gen;
        unsigned arrived = atomicAdd(&g_bar_count, 1u);
        if (arrived == gridDim.x - 1) {
            g_bar_count = 0;
            __threadfence();
            atomicAdd(&g_bar_gen, 1u);
        } else {
            while (*(volatile unsigned*)&g_bar_gen == gen) {}
        }
        __threadfence();
    }
    __syncthreads();
}

__device__ __forceinline__ void flush_stats(float accs, float accq, int sumoff) {
    __shared__ float ss[4][32], sq[4][32];
    int lane = threadIdx.x & 31;
    int w    = threadIdx.x >> 5;
    ss[w][lane] = accs;
    sq[w][lane] = accq;
    __syncthreads();
    if (threadIdx.x < 32) {
        float s = 0.f, q = 0.f;
        #pragma unroll
        for (int k = 0; k < 4; k++) { s += ss[k][lane]; q += sq[k][lane]; }
        atomicAdd(&g_sums[sumoff + lane],      s);
        atomicAdd(&g_sums[sumoff + 32 + lane], q);
        __threadfence();
    }
    __syncthreads();
}

// == FUSED 1: encode+hist -> bar -> prep+scan -> bar -> offsets -> bar -> scatter ==
__global__ void __launch_bounds__(128, 4) k_enc_prep(
        const float* __restrict__ x_cont, const int* __restrict__ x_cat,
        const float* __restrict__ datanorm,
        const float* __restrict__ W_cont, const float* __restrict__ b_cont,
        const float* __restrict__ emb_charge, const float* __restrict__ emb_pdg,
        const float* __restrict__ W_cat, const float* __restrict__ b_cat,
        const float* __restrict__ W_enc, const float* __restrict__ b_enc,
        const float* __restrict__ g_all, const float* __restrict__ be_all,
        const float* __restrict__ W_msg,
        const int* __restrict__ ei, int E, int N)
{
    int tid  = threadIdx.x;
    int lane = tid & 31;
    int w    = tid >> 5;
    int l16  = lane & 15;
    bool hi  = lane >= 16;
    int gw   = (blockIdx.x * blockDim.x + tid) >> 5;
    int nw   = (gridDim.x * blockDim.x) >> 5;
    int T    = gridDim.x * blockDim.x;
    int gtid = blockIdx.x * blockDim.x + tid;

    __shared__ __align__(16) u64 s_c [4][16];
    __shared__ __align__(16) u64 s_x [4][8];
    __shared__ __align__(16) u64 s_in[4][32];

    // ---------------- phase A: encoder + BN1 stats + edge histogram ---------
    {
        u64 wcat2[16], wcont2[6], wenc2[32];
        #pragma unroll
        for (int j = 0; j < 16; j++) { float v = W_cat[j * 16 + l16];  wcat2[j]  = pack2(v, v); }
        #pragma unroll
        for (int j = 0; j < 6; j++)  { float v = W_cont[j * 16 + l16]; wcont2[j] = pack2(v, v); }
        #pragma unroll
        for (int j = 0; j < 32; j++) { float v = W_enc[j * 32 + lane]; wenc2[j]  = pack2(v, v); }
        float bcat  = b_cat[l16];
        float bcont = b_cont[l16];
        float benc  = b_enc[lane];
        float dn    = (lane < 6) ? datanorm[lane] : 0.f;

        float accs = 0.f, accq = 0.f;

        for (long long n0 = (long long)gw * 2; n0 < N; n0 += (long long)nw * 2) {
            int na = (int)n0;
            bool hasb = (na + 1 < N);
            int nb = hasb ? na + 1 : na;

            if (!hi) {
                int2 ca = __ldg((const int2*)x_cat + na);
                int2 cb = __ldg((const int2*)x_cat + nb);
                int pa = ca.x < 0 ? -ca.x : ca.x;
                int pb = cb.x < 0 ? -cb.x : cb.x;
                int pia = (pa == 1) ? 0 : (pa == 2) ? 1 : (pa == 11) ? 2 : (pa == 13) ? 3
                        : (pa == 22) ? 4 : (pa == 130) ? 5 : 6;
                int pib = (pb == 1) ? 0 : (pb == 2) ? 1 : (pb == 11) ? 2 : (pb == 13) ? 3
                        : (pb == 22) ? 4 : (pb == 130) ? 5 : 6;
                float c0a = (lane < 8) ? emb_charge[(ca.y + 1) * 8 + lane] : emb_pdg[pia * 8 + lane - 8];
                float c0b = (lane < 8) ? emb_charge[(cb.y + 1) * 8 + lane] : emb_pdg[pib * 8 + lane - 8];
                s_c[w][lane] = pack2(c0a, c0b);
                if (lane < 6) {
                    float xa = x_cont[(long long)na * 6 + lane] * dn;
                    float xb = x_cont[(long long)nb * 6 + lane] * dn;
                    s_x[w][lane] = pack2(xa, xb);
                }
            }
            __syncwarp();

            u64 in2;
            if (!hi) {
                u64 a0 = pack2(bcat, bcat), a1 = pack2(0.f, 0.f);
                const ulonglong2* p = (const ulonglong2*)s_c[w];
                #pragma unroll
                for (int i = 0; i < 4; i++) {
                    ulonglong2 qa = p[i];
                    ulonglong2 qb = p[i + 4];
                    a0 = ffma2(qa.x, wcat2[2 * i], a0);
                    a0 = ffma2(qa.y, wcat2[2 * i + 1], a0);
                    a1 = ffma2(qb.x, wcat2[2 * i + 8], a1);
                    a1 = ffma2(qb.y, wcat2[2 * i + 9], a1);
                }
                u64 acc = add2(a0, a1);
                float v0, v1; unpack2(acc, v0, v1);
                in2 = pack2(eluf(v0), eluf(v1));
            } else {
                u64 acc = pack2(bcont, bcont);
                const ulonglong2* p = (const ulonglong2*)s_x[w];
                #pragma unroll
                for (int i = 0; i < 3; i++) {
                    ulonglong2 q = p[i];
                    acc = ffma2(q.x, wcont2[2 * i], acc);
                    acc = ffma2(q.y, wcont2[2 * i + 1], acc);
                }
                float v0, v1; unpack2(acc, v0, v1);
                in2 = pack2(eluf(v0), eluf(v1));
            }
            s_in[w][lane] = in2;
            __syncwarp();

            u64 a0 = pack2(benc, benc), a1 = pack2(0.f, 0.f);
            {
                const ulonglong2* p = (const ulonglong2*)s_in[w];
                #pragma unroll
                for (int i = 0; i < 8; i++) {
                    ulonglong2 qa = p[i];
                    ulonglong2 qb = p[i + 8];
                    a0 = ffma2(qa.x, wenc2[2 * i], a0);
                    a0 = ffma2(qa.y, wenc2[2 * i + 1], a0);
                    a1 = ffma2(qb.x, wenc2[2 * i + 16], a1);
                    a1 = ffma2(qb.y, wenc2[2 * i + 17], a1);
                }
            }
            u64 acc = add2(a0, a1);
            float ha, hb; unpack2(acc, ha, hb);
            ha = eluf(ha); hb = eluf(hb);

            g_emb[(long long)na * 32 + lane] = ha;
            accs += ha; accq += ha * ha;
            if (hasb) {
                g_emb[(long long)nb * 32 + lane] = hb;
                accs += hb; accq += hb * hb;
            }
            __syncwarp();
        }
        flush_stats(accs, accq, 0);

        // edge histogram over dst
        for (int idx = gtid; idx < E; idx += T)
            atomicAdd(&g_deg[__ldg(&ei[E + idx])], 1);
    }

    grid_barrier();

    // ---------------- phase B: u,v with BN1 folded + local deg scan ---------
    {
        float wd[32], wb[32];
        #pragma unroll
        for (int j = 0; j < 32; j++) {
            float a = W_msg[j * 32 + lane];
            float b = W_msg[1024 + j * 32 + lane];
            wd[j] = a - b;
            wb[j] = b;
        }
        float m    = g_sums[lane] / (float)N;
        float var  = g_sums[32 + lane] / (float)N - m * m;
        float inv  = rsqrtf(var + BN_EPS);
        float ga   = g_all[lane];
        float scale = ga * inv;
        float shift = be_all[lane] - m * ga * inv;

        float cu = 0.f, cv = 0.f;
        u64 w2[32];
        #pragma unroll
        for (int j = 0; j < 32; j++) {
            float sj = __shfl_sync(0xffffffffu, scale, j);
            float tj = __shfl_sync(0xffffffffu, shift, j);
            cu += tj * wd[j];
            cv += tj * wb[j];
            w2[j] = pack2(wd[j] * sj, wb[j] * sj);
        }
        u64 base = pack2(cu, cv);
        const u64 zz = pack2(0.f, 0.f);

        __shared__ __align__(16) u64 s_h[4][2][32];

        long long n0 = (long long)gw * 2;
        float ha = (n0 < N) ? g_emb[n0 * 32 + lane] : 0.f;
        float hb = (n0 + 1 < N) ? g_emb[(n0 + 1) * 32 + lane] : ha;

        for (; n0 < N; n0 += (long long)nw * 2) {
            int na = (int)n0;
            bool hasb = (na + 1 < N);
            int nb = hasb ? na + 1 : na;

            s_h[w][0][lane] = pack2(ha, ha);
            s_h[w][1][lane] = pack2(hb, hb);
            __syncwarp();

            long long nn = n0 + (long long)nw * 2;
            float nha = 0.f, nhb = 0.f;
            if (nn < N) {
                nha = g_emb[nn * 32 + lane];
                nhb = (nn + 1 < N) ? g_emb[(nn + 1) * 32 + lane] : nha;
            }

            u64 a0 = base, a1 = zz, b0 = base, b1 = zz;
            const ulonglong2* p0 = (const ulonglong2*)s_h[w][0];
            const ulonglong2* p1 = (const ulonglong2*)s_h[w][1];
            #pragma unroll
            for (int i = 0; i < 8; i++) {
                ulonglong2 qa = p0[i];
                ulonglong2 qb = p0[i + 8];
                a0 = ffma2(qa.x, w2[2 * i], a0);
                a0 = ffma2(qa.y, w2[2 * i + 1], a0);
                a1 = ffma2(qb.x, w2[2 * i + 16], a1);
                a1 = ffma2(qb.y, w2[2 * i + 17], a1);
                ulonglong2 ra = p1[i];
                ulonglong2 rb = p1[i + 8];
                b0 = ffma2(ra.x, w2[2 * i], b0);
                b0 = ffma2(ra.y, w2[2 * i + 1], b0);
                b1 = ffma2(rb.x, w2[2 * i + 16], b1);
                b1 = ffma2(rb.y, w2[2 * i + 17], b1);
            }
            u64 acc0 = add2(a0, a1);
            u64 acc1 = add2(b0, b1);
            float u0, v0; unpack2(acc0, u0, v0);
            g_u[(long long)na * 32 + lane] = u0;
            g_v[(long long)na * 32 + lane] = v0;
            if (hasb) {
                float u1, v1; unpack2(acc1, u1, v1);
                g_u[(long long)nb * 32 + lane] = u1;
                g_v[(long long)nb * 32 + lane] = v1;
            }
            ha = nha; hb = nhb;
            __syncwarp();
        }

        // local scan of this block's deg chunk
        __shared__ int s_deg[256];
        int CH = (N + gridDim.x - 1) / gridDim.x;   // <= 170 for N <= NMAX
        int bn = blockIdx.x * CH;
        __syncthreads();
        for (int i = tid; i < CH; i += 128) {
            int n = bn + i;
            s_deg[i] = (n < N) ? g_deg[n] : 0;
        }
        __syncthreads();
        if (tid == 0) {
            int acc = 0;
            for (int i = 0; i < CH; i++) {
                int n = bn + i;
                if (n < N) g_off[n] = acc;
                acc += s_deg[i];
            }
            g_btot[blockIdx.x] = acc;
        }
    }

    grid_barrier();

    // ---------------- phase C: add block base offsets ------------------------
    {
        __shared__ int s_part[128];
        __shared__ int s_base;
        int ssum = 0;
        for (int i = tid; i < blockIdx.x; i += 128) ssum += g_btot[i];
        s_part[tid] = ssum;
        __syncthreads();
        if (tid < 32) {
            int v = s_part[tid] + s_part[tid + 32] + s_part[tid + 64] + s_part[tid + 96];
            #pragma unroll
            for (int off = 16; off; off >>= 1) v += __shfl_down_sync(0xffffffffu, v, off);
            if (tid == 0) s_base = v;
        }
        __syncthreads();
        int bbase = s_base;
        int CH = (N + gridDim.x - 1) / gridDim.x;
        int bn = blockIdx.x * CH;
        for (int i = tid; i < CH; i += 128) {
            int n = bn + i;
            if (n < N) {
                int o = g_off[n] + bbase;
                g_off[n] = o;
                g_cur[n] = o;
            }
        }
    }

    grid_barrier();

    // ---------------- phase D: scatter src into CSR ---------------------------
    for (int idx = gtid; idx < E; idx += T) {
        int s = __ldg(&ei[idx]);
        int d = __ldg(&ei[E + idx]);
        int pos = atomicAdd(&g_cur[d], 1);
        g_csr[pos] = s;
    }
}

// == FUSED 2: CSR pull-max + agg + BN2 stats -> barrier -> output MLP =========
__global__ void __launch_bounds__(128, 6) k_max_out(
        const float* __restrict__ g_all, const float* __restrict__ be_all,
        const float* __restrict__ b_msg,
        const float* __restrict__ g_conv, const float* __restrict__ be_conv,
        const float* __restrict__ W_o1, const float* __restrict__ b_o1,
        const float* __restrict__ W_o2, const float* __restrict__ b_o2,
        float* __restrict__ out, int N)
{
    int lane = threadIdx.x & 31;
    int w    = threadIdx.x >> 5;
    int l16  = lane & 15;
    int gw   = blockIdx.x * 4 + w;
    int nwarps = gridDim.x * 4;
    int chunk  = (N + nwarps - 1) / nwarps;      // <= 29 for N <= NMAX
    int n_start = gw * chunk;
    int cnt = N - n_start;
    if (cnt > chunk) cnt = chunk;
    if (cnt < 0) cnt = 0;

    __shared__ float s_agg[4][32][32];
    __shared__ float s_h[4][66];

    float bmr = b_msg[lane];

    // ---------------- phase A: pull-max over CSR + BN2 stats ----------------
    {
        float accs = 0.f, accq = 0.f;
        const float ninf = __int_as_float(0xff800000);
        for (int i = 0; i < cnt; i++) {
            int n = n_start + i;
            int off = __ldg(&g_off[n]);
            int deg = __ldg(&g_deg[n]);
            float m = ninf;
            for (int b = 0; b < deg; b += 32) {
                int k = deg - b; if (k > 32) k = 32;
                int e = (lane < k) ? __ldg(&g_csr[off + b + lane]) : 0;
                #pragma unroll 4
                for (int j = 0; j < k; j++) {
                    int s = __shfl_sync(0xffffffffu, e, j);
                    m = fmaxf(m, __ldg(&g_v[(long long)s * 32 + lane]));
                }
            }
            float uval = g_u[(long long)n * 32 + lane];
            float x = (deg > 0) ? (uval + bmr + m) : 0.f;
            s_agg[w][i][lane] = x;
            accs += x;
            accq += x * x;
        }
        flush_stats(accs, accq, 64);
    }

    grid_barrier();

    // ---------------- phase B: residual + output MLP (split-lane) -----------
    {
        float w1[32];
        #pragma unroll
        for (int j = 0; j < 32; j++) w1[j] = W_o1[j * 16 + l16];
        float w2s = W_o2[l16];
        float b1  = b_o1[l16];
        float b2  = b_o2[0];

        float m1    = g_sums[lane] / (float)N;
        float var1  = g_sums[32 + lane] / (float)N - m1 * m1;
        float inv1  = rsqrtf(var1 + BN_EPS);
        float ga    = g_all[lane];
        float scale1 = ga * inv1;
        float shift1 = be_all[lane] - m1 * ga * inv1;

        float m2    = g_sums[64 + lane] / (float)N;
        float var2  = g_sums[96 + lane] / (float)N - m2 * m2;
        float inv2  = rsqrtf(var2 + BN_EPS);
        float gc    = g_conv[lane];
        float scale2 = gc * inv2;
        float shift2 = be_conv[lane] - m2 * gc * inv2;

        int base = (lane < 16) ? 0 : 33;

        for (int i = 0; i < cnt; i += 2) {
            long long na = (long long)(n_start + i);
            bool hasb = (i + 1 < cnt);

            float hraw_a = g_emb[na * 32 + lane];
            float hraw_b = hasb ? g_emb[(na + 1) * 32 + lane] : 0.f;
            float h_a = (hraw_a * scale1 + shift1) + (s_agg[w][i][lane] * scale2 + shift2);
            float h_b = hasb ? (hraw_b * scale1 + shift1) + (s_agg[w][i + 1][lane] * scale2 + shift2) : 0.f;

            s_h[w][lane]      = h_a;
            s_h[w][33 + lane] = h_b;
            __syncwarp();

            float a0 = b1, a1 = 0.f;
            #pragma unroll
            for (int j = 0; j < 16; j++) {
                a0 += s_h[w][base + j]      * w1[j];
                a1 += s_h[w][base + 16 + j] * w1[16 + j];
            }
            float o = eluf(a0 + a1) * w2s;
            #pragma unroll
            for (int off = 1; off < 16; off <<= 1)
                o += __shfl_xor_sync(0xffffffffu, o, off);
            if (lane == 0)          out[na]     = o + b2;
            if (lane == 16 && hasb) out[na + 1] = o + b2;
            __syncwarp();
        }
    }
}

extern "C" void kernel_launch(void* const* d_in, const int* in_sizes, int n_in,
                              void* d_out, int out_size)
{
    const float* x_cont     = (const float*)d_in[0];
    const int*   x_cat      = (const int*)  d_in[1];
    const int*   edge_index = (const int*)  d_in[2];
    const float* datanorm   = (const float*)d_in[4];
    const float* W_cont     = (const float*)d_in[5];
    const float* b_cont     = (const float*)d_in[6];
    const float* emb_charge = (const float*)d_in[7];
    const float* emb_pdg    = (const float*)d_in[8];
    const float* W_cat      = (const float*)d_in[9];
    const float* b_cat      = (const float*)d_in[10];
    const float* W_enc      = (const float*)d_in[11];
    const float* b_enc      = (const float*)d_in[12];
    const float* g_all      = (const float*)d_in[13];
    const float* be_all     = (const float*)d_in[14];
    const float* W_msg      = (const float*)d_in[15];
    const float* b_msg      = (const float*)d_in[16];
    const float* g_conv     = (const float*)d_in[17];
    const float* be_conv    = (const float*)d_in[18];
    const float* W_o1       = (const float*)d_in[19];
    const float* b_o1       = (const float*)d_in[20];
    const float* W_o2       = (const float*)d_in[21];
    const float* b_o2       = (const float*)d_in[22];
    float* out = (float*)d_out;

    int N = in_sizes[0] / 6;
    int E = in_sizes[2] / 2;

    k_zero<<<128, 1024>>>(N);
    k_enc_prep<<<592, 128>>>(x_cont, x_cat, datanorm, W_cont, b_cont,
                             emb_charge, emb_pdg, W_cat, b_cat, W_enc, b_enc,
                             g_all, be_all, W_msg, edge_index, E, N);
    k_max_out<<<888, 128>>>(g_all, be_all, b_msg, g_conv, be_conv,
                            W_o1, b_o1, W_o2, b_o2, out, N);
}

// round 11
// speedup vs baseline: 1.4213x; 1.4213x over previous
#include <cuda_runtime.h>
#include <math.h>

#define NMAX 100352
#define BN_EPS 1e-3f

__device__ float g_emb [NMAX * 32];
__device__ float g_u   [NMAX * 32];
__device__ float g_v   [NMAX * 32];
__device__ float g_max [NMAX * 32];
__device__ float g_sums[128];      // fp32 stats: [0:32) s1, [32:64) q1, [64:96) s2, [96:128) q2

__device__ unsigned g_bar_count = 0;
__device__ unsigned g_bar_gen   = 0;

typedef unsigned long long u64;

__device__ __forceinline__ u64 pack2(float x, float y) {
    u64 r; asm("mov.b64 %0, {%1, %2};" : "=l"(r) : "f"(x), "f"(y)); return r;
}
__device__ __forceinline__ void unpack2(u64 v, float& x, float& y) {
    asm("mov.b64 {%0, %1}, %2;" : "=f"(x), "=f"(y) : "l"(v));
}
__device__ __forceinline__ u64 ffma2(u64 a, u64 b, u64 c) {
    u64 d; asm("fma.rn.f32x2 %0, %1, %2, %3;" : "=l"(d) : "l"(a), "l"(b), "l"(c)); return d;
}
__device__ __forceinline__ u64 add2(u64 a, u64 b) {
    u64 d; asm("add.rn.f32x2 %0, %1, %2;" : "=l"(d) : "l"(a), "l"(b)); return d;
}
__device__ __forceinline__ float eluf(float x) { return x > 0.f ? x : expm1f(x); }

__global__ void k_zero() {
    if (threadIdx.x < 128) g_sums[threadIdx.x] = 0.f;
}

// all blocks must be resident (grid == guaranteed-resident capacity via launch_bounds)
__device__ __forceinline__ void grid_barrier() {
    __syncthreads();
    if (threadIdx.x == 0) {
        __threadfence();
        unsigned gen = *(volatile unsigned*)&g_bar_gen;
        unsigned arrived = atomicAdd(&g_bar_count, 1u);
        if (arrived == gridDim.x - 1) {
            g_bar_count = 0;
            __threadfence();
            atomicAdd(&g_bar_gen, 1u);
        } else {
            while (*(volatile unsigned*)&g_bar_gen == gen) {}
        }
        __threadfence();
    }
    __syncthreads();
}

__device__ __forceinline__ void flush_stats(float accs, float accq, int sumoff) {
    __shared__ float ss[4][32], sq[4][32];
    int lane = threadIdx.x & 31;
    int w    = threadIdx.x >> 5;
    ss[w][lane] = accs;
    sq[w][lane] = accq;
    __syncthreads();
    if (threadIdx.x < 32) {
        float s = 0.f, q = 0.f;
        #pragma unroll
        for (int k = 0; k < 4; k++) { s += ss[k][lane]; q += sq[k][lane]; }
        atomicAdd(&g_sums[sumoff + lane],      s);
        atomicAdd(&g_sums[sumoff + 32 + lane], q);
        __threadfence();
    }
    __syncthreads();
}

// ================= FUSED 1: encode -> BN1 stats -> barrier -> prep ==========
__global__ void __launch_bounds__(128, 4) k_enc_prep(
        const float* __restrict__ x_cont, const int* __restrict__ x_cat,
        const float* __restrict__ datanorm,
        const float* __restrict__ W_cont, const float* __restrict__ b_cont,
        const float* __restrict__ emb_charge, const float* __restrict__ emb_pdg,
        const float* __restrict__ W_cat, const float* __restrict__ b_cat,
        const float* __restrict__ W_enc, const float* __restrict__ b_enc,
        const float* __restrict__ g_all, const float* __restrict__ be_all,
        const float* __restrict__ W_msg, int N)
{
    int lane = threadIdx.x & 31;
    int w    = threadIdx.x >> 5;
    int l16  = lane & 15;
    bool hi  = lane >= 16;
    int gw   = (blockIdx.x * blockDim.x + threadIdx.x) >> 5;
    int nw   = (gridDim.x * blockDim.x) >> 5;

    __shared__ __align__(16) u64 s_c [4][16];
    __shared__ __align__(16) u64 s_x [4][8];
    __shared__ __align__(16) u64 s_in[4][32];

    // ---------------- phase A: encoder ----------------
    {
        u64 wcat2[16], wcont2[6], wenc2[32];
        #pragma unroll
        for (int j = 0; j < 16; j++) { float v = W_cat[j * 16 + l16];  wcat2[j]  = pack2(v, v); }
        #pragma unroll
        for (int j = 0; j < 6; j++)  { float v = W_cont[j * 16 + l16]; wcont2[j] = pack2(v, v); }
        #pragma unroll
        for (int j = 0; j < 32; j++) { float v = W_enc[j * 32 + lane]; wenc2[j]  = pack2(v, v); }
        float bcat  = b_cat[l16];
        float bcont = b_cont[l16];
        float benc  = b_enc[lane];
        float dn    = (lane < 6) ? datanorm[lane] : 0.f;

        const float ninf = __int_as_float(0xff800000);
        float accs = 0.f, accq = 0.f;

        for (long long n0 = (long long)gw * 2; n0 < N; n0 += (long long)nw * 2) {
            int na = (int)n0;
            bool hasb = (na + 1 < N);
            int nb = hasb ? na + 1 : na;

            if (!hi) {
                int2 ca = __ldg((const int2*)x_cat + na);
                int2 cb = __ldg((const int2*)x_cat + nb);
                int pa = ca.x < 0 ? -ca.x : ca.x;
                int pb = cb.x < 0 ? -cb.x : cb.x;
                int pia = (pa == 1) ? 0 : (pa == 2) ? 1 : (pa == 11) ? 2 : (pa == 13) ? 3
                        : (pa == 22) ? 4 : (pa == 130) ? 5 : 6;
                int pib = (pb == 1) ? 0 : (pb == 2) ? 1 : (pb == 11) ? 2 : (pb == 13) ? 3
                        : (pb == 22) ? 4 : (pb == 130) ? 5 : 6;
                float c0a = (lane < 8) ? emb_charge[(ca.y + 1) * 8 + lane] : emb_pdg[pia * 8 + lane - 8];
                float c0b = (lane < 8) ? emb_charge[(cb.y + 1) * 8 + lane] : emb_pdg[pib * 8 + lane - 8];
                s_c[w][lane] = pack2(c0a, c0b);
                if (lane < 6) {
                    float xa = x_cont[(long long)na * 6 + lane] * dn;
                    float xb = x_cont[(long long)nb * 6 + lane] * dn;
                    s_x[w][lane] = pack2(xa, xb);
                }
            }
            __syncwarp();

            u64 in2;
            if (!hi) {
                u64 a0 = pack2(bcat, bcat), a1 = pack2(0.f, 0.f);
                const ulonglong2* p = (const ulonglong2*)s_c[w];
                #pragma unroll
                for (int i = 0; i < 4; i++) {
                    ulonglong2 qa = p[i];
                    ulonglong2 qb = p[i + 4];
                    a0 = ffma2(qa.x, wcat2[2 * i], a0);
                    a0 = ffma2(qa.y, wcat2[2 * i + 1], a0);
                    a1 = ffma2(qb.x, wcat2[2 * i + 8], a1);
                    a1 = ffma2(qb.y, wcat2[2 * i + 9], a1);
                }
                u64 acc = add2(a0, a1);
                float v0, v1; unpack2(acc, v0, v1);
                in2 = pack2(eluf(v0), eluf(v1));
            } else {
                u64 acc = pack2(bcont, bcont);
                const ulonglong2* p = (const ulonglong2*)s_x[w];
                #pragma unroll
                for (int i = 0; i < 3; i++) {
                    ulonglong2 q = p[i];
                    acc = ffma2(q.x, wcont2[2 * i], acc);
                    acc = ffma2(q.y, wcont2[2 * i + 1], acc);
                }
                float v0, v1; unpack2(acc, v0, v1);
                in2 = pack2(eluf(v0), eluf(v1));
            }
            s_in[w][lane] = in2;
            __syncwarp();

            u64 a0 = pack2(benc, benc), a1 = pack2(0.f, 0.f);
            {
                const ulonglong2* p = (const ulonglong2*)s_in[w];
                #pragma unroll
                for (int i = 0; i < 8; i++) {
                    ulonglong2 qa = p[i];
                    ulonglong2 qb = p[i + 8];
                    a0 = ffma2(qa.x, wenc2[2 * i], a0);
                    a0 = ffma2(qa.y, wenc2[2 * i + 1], a0);
                    a1 = ffma2(qb.x, wenc2[2 * i + 16], a1);
                    a1 = ffma2(qb.y, wenc2[2 * i + 17], a1);
                }
            }
            u64 acc = add2(a0, a1);
            float ha, hb; unpack2(acc, ha, hb);
            ha = eluf(ha); hb = eluf(hb);

            g_emb[(long long)na * 32 + lane] = ha;
            g_max[(long long)na * 32 + lane] = ninf;
            accs += ha; accq += ha * ha;
            if (hasb) {
                g_emb[(long long)nb * 32 + lane] = hb;
                g_max[(long long)nb * 32 + lane] = ninf;
                accs += hb; accq += hb * hb;
            }
            __syncwarp();
        }
        flush_stats(accs, accq, 0);
    }

    grid_barrier();

    // ---------------- phase B: u,v with BN1 folded ----------------
    {
        float wd[32], wb[32];
        #pragma unroll
        for (int j = 0; j < 32; j++) {
            float a = W_msg[j * 32 + lane];
            float b = W_msg[1024 + j * 32 + lane];
            wd[j] = a - b;
            wb[j] = b;
        }
        float m    = g_sums[lane] / (float)N;
        float var  = g_sums[32 + lane] / (float)N - m * m;
        float inv  = rsqrtf(var + BN_EPS);
        float ga   = g_all[lane];
        float scale = ga * inv;
        float shift = be_all[lane] - m * ga * inv;

        float cu = 0.f, cv = 0.f;
        u64 w2[32];
        #pragma unroll
        for (int j = 0; j < 32; j++) {
            float sj = __shfl_sync(0xffffffffu, scale, j);
            float tj = __shfl_sync(0xffffffffu, shift, j);
            cu += tj * wd[j];
            cv += tj * wb[j];
            w2[j] = pack2(wd[j] * sj, wb[j] * sj);
        }
        u64 base = pack2(cu, cv);
        const u64 zz = pack2(0.f, 0.f);

        __shared__ __align__(16) u64 s_h[4][2][32];

        long long n0 = (long long)gw * 2;
        float ha = (n0 < N) ? g_emb[n0 * 32 + lane] : 0.f;
        float hb = (n0 + 1 < N) ? g_emb[(n0 + 1) * 32 + lane] : ha;

        for (; n0 < N; n0 += (long long)nw * 2) {
            int na = (int)n0;
            bool hasb = (na + 1 < N);
            int nb = hasb ? na + 1 : na;

            s_h[w][0][lane] = pack2(ha, ha);
            s_h[w][1][lane] = pack2(hb, hb);
            __syncwarp();

            long long nn = n0 + (long long)nw * 2;
            float nha = 0.f, nhb = 0.f;
            if (nn < N) {
                nha = g_emb[nn * 32 + lane];
                nhb = (nn + 1 < N) ? g_emb[(nn + 1) * 32 + lane] : nha;
            }

            u64 a0 = base, a1 = zz, b0 = base, b1 = zz;
            const ulonglong2* p0 = (const ulonglong2*)s_h[w][0];
            const ulonglong2* p1 = (const ulonglong2*)s_h[w][1];
            #pragma unroll
            for (int i = 0; i < 8; i++) {
                ulonglong2 qa = p0[i];
                ulonglong2 qb = p0[i + 8];
                a0 = ffma2(qa.x, w2[2 * i], a0);
                a0 = ffma2(qa.y, w2[2 * i + 1], a0);
                a1 = ffma2(qb.x, w2[2 * i + 16], a1);
                a1 = ffma2(qb.y, w2[2 * i + 17], a1);
                ulonglong2 ra = p1[i];
                ulonglong2 rb = p1[i + 8];
                b0 = ffma2(ra.x, w2[2 * i], b0);
                b0 = ffma2(ra.y, w2[2 * i + 1], b0);
                b1 = ffma2(rb.x, w2[2 * i + 16], b1);
                b1 = ffma2(rb.y, w2[2 * i + 17], b1);
            }
            u64 acc0 = add2(a0, a1);
            u64 acc1 = add2(b0, b1);
            float u0, v0; unpack2(acc0, u0, v0);
            g_u[(long long)na * 32 + lane] = u0;
            g_v[(long long)na * 32 + lane] = v0;
            if (hasb) {
                float u1, v1; unpack2(acc1, u1, v1);
                g_u[(long long)nb * 32 + lane] = u1;
                g_v[(long long)nb * 32 + lane] = v1;
            }
            ha = nha; hb = nhb;
            __syncwarp();
        }
    }
}

// ---------------- K3: edge atomic max (proven config + __ldg pre-read) ------
__device__ __forceinline__ void amax1(float* a, float v, float c) {
    if (v > c) {
        if (__float_as_int(v) >= 0) atomicMax((int*)a, __float_as_int(v));
        else                        atomicMin((unsigned int*)a, __float_as_uint(v));
    }
}

__global__ void __launch_bounds__(256) k_edge(const int* __restrict__ ei, int E, int NP)
{
    int tid = blockIdx.x * blockDim.x + threadIdx.x;
    int c  = tid & 7;
    int pe = tid >> 3;
    if (pe >= NP) return;
    int e0 = pe * 2;
    bool has1 = (e0 + 1 < E);

    int s0, s1, d0, d1;
    if ((E & 1) == 0) {
        int2 ss = __ldg((const int2*)(ei + e0));
        int2 dd = __ldg((const int2*)(ei + E + e0));
        s0 = ss.x; s1 = ss.y;
        d0 = dd.x; d1 = dd.y;
    } else {
        s0 = __ldg(&ei[e0]);
        d0 = __ldg(&ei[E + e0]);
        s1 = has1 ? __ldg(&ei[e0 + 1])     : s0;
        d1 = has1 ? __ldg(&ei[E + e0 + 1]) : d0;
    }

    const float4* v4 = (const float4*)g_v;
    const float4* m4 = (const float4*)g_max;

    float4 val0 = __ldg(&v4[(long long)s0 * 8 + c]);
    float4 val1 = __ldg(&v4[(long long)s1 * 8 + c]);
    // monotone buffer: stale pre-read only causes a redundant atomic, never a miss
    float4 cur0 = __ldg(&m4[(long long)d0 * 8 + c]);
    float4 cur1 = __ldg(&m4[(long long)d1 * 8 + c]);

    float* a0 = &g_max[(long long)d0 * 32 + c * 4];
    amax1(a0 + 0, val0.x, cur0.x);
    amax1(a0 + 1, val0.y, cur0.y);
    amax1(a0 + 2, val0.z, cur0.z);
    amax1(a0 + 3, val0.w, cur0.w);
    if (has1) {
        float* a1 = &g_max[(long long)d1 * 32 + c * 4];
        amax1(a1 + 0, val1.x, cur1.x);
        amax1(a1 + 1, val1.y, cur1.y);
        amax1(a1 + 2, val1.z, cur1.z);
        amax1(a1 + 3, val1.w, cur1.w);
    }
}

// ========= FUSED 2: agg stats (stash agg) -> barrier -> output MLP ==========
// 8 blocks/SM (1184 blocks, 4736 warps); chunk = ceil(N/4736) <= 22 for N <= NMAX
__global__ void __launch_bounds__(128, 8) k_agg_out(
        const float* __restrict__ g_all, const float* __restrict__ be_all,
        const float* __restrict__ b_msg,
        const float* __restrict__ g_conv, const float* __restrict__ be_conv,
        const float* __restrict__ W_o1, const float* __restrict__ b_o1,
        const float* __restrict__ W_o2, const float* __restrict__ b_o2,
        float* __restrict__ out, int N)
{
    int lane = threadIdx.x & 31;
    int w    = threadIdx.x >> 5;
    int l16  = lane & 15;
    int gw   = blockIdx.x * 4 + w;
    int nwarps = gridDim.x * 4;
    int chunk  = (N + nwarps - 1) / nwarps;
    int n_start = gw * chunk;
    int cnt = N - n_start;
    if (cnt > chunk) cnt = chunk;
    if (cnt < 0) cnt = 0;

    __shared__ float s_agg[4][22][32];   // [warp][node-in-chunk][feature]
    __shared__ float s_h[4][66];         // node a at [0..32), node b at [33..65)

    float bmr = b_msg[lane];

    // ---------------- phase A: agg + BN2 stats, stash agg in smem -----------
    {
        float accs = 0.f, accq = 0.f;
        for (int i = 0; i < cnt; i++) {
            long long n = (long long)(n_start + i);
            float mval = g_max[n * 32 + lane];
            float uval = g_u[n * 32 + lane];
            int m0 = __shfl_sync(0xffffffffu, __float_as_int(mval), 0);
            float x = (m0 == (int)0xff800000) ? 0.f : (uval + bmr + mval);
            s_agg[w][i][lane] = x;
            accs += x;
            accq += x * x;
        }
        flush_stats(accs, accq, 64);
    }

    grid_barrier();

    // ---------------- phase B: residual + output MLP (split-lane) -----------
    {
        float w1[32];
        #pragma unroll
        for (int j = 0; j < 32; j++) w1[j] = W_o1[j * 16 + l16];
        float w2s = W_o2[l16];
        float b1  = b_o1[l16];
        float b2  = b_o2[0];

        float m1    = g_sums[lane] / (float)N;
        float var1  = g_sums[32 + lane] / (float)N - m1 * m1;
        float inv1  = rsqrtf(var1 + BN_EPS);
        float ga    = g_all[lane];
        float scale1 = ga * inv1;
        float shift1 = be_all[lane] - m1 * ga * inv1;

        float m2    = g_sums[64 + lane] / (float)N;
        float var2  = g_sums[96 + lane] / (float)N - m2 * m2;
        float inv2  = rsqrtf(var2 + BN_EPS);
        float gc    = g_conv[lane];
        float scale2 = gc * inv2;
        float shift2 = be_conv[lane] - m2 * gc * inv2;

        int base = (lane < 16) ? 0 : 33;

        for (int i = 0; i < cnt; i += 2) {
            long long na = (long long)(n_start + i);
            bool hasb = (i + 1 < cnt);

            float hraw_a = g_emb[na * 32 + lane];
            float hraw_b = hasb ? g_emb[(na + 1) * 32 + lane] : 0.f;
            float h_a = (hraw_a * scale1 + shift1) + (s_agg[w][i][lane] * scale2 + shift2);
            float h_b = hasb ? (hraw_b * scale1 + shift1) + (s_agg[w][i + 1][lane] * scale2 + shift2) : 0.f;

            s_h[w][lane]      = h_a;
            s_h[w][33 + lane] = h_b;
            __syncwarp();

            float a0 = b1, a1 = 0.f;
            #pragma unroll
            for (int j = 0; j < 16; j++) {
                a0 += s_h[w][base + j]      * w1[j];
                a1 += s_h[w][base + 16 + j] * w1[16 + j];
            }
            float o = eluf(a0 + a1) * w2s;
            #pragma unroll
            for (int off = 1; off < 16; off <<= 1)
                o += __shfl_xor_sync(0xffffffffu, o, off);
            if (lane == 0)          out[na]     = o + b2;
            if (lane == 16 && hasb) out[na + 1] = o + b2;
            __syncwarp();
        }
    }
}

extern "C" void kernel_launch(void* const* d_in, const int* in_sizes, int n_in,
                              void* d_out, int out_size)
{
    const float* x_cont     = (const float*)d_in[0];
    const int*   x_cat      = (const int*)  d_in[1];
    const int*   edge_index = (const int*)  d_in[2];
    const float* datanorm   = (const float*)d_in[4];
    const float* W_cont     = (const float*)d_in[5];
    const float* b_cont     = (const float*)d_in[6];
    const float* emb_charge = (const float*)d_in[7];
    const float* emb_pdg    = (const float*)d_in[8];
    const float* W_cat      = (const float*)d_in[9];
    const float* b_cat      = (const float*)d_in[10];
    const float* W_enc      = (const float*)d_in[11];
    const float* b_enc      = (const float*)d_in[12];
    const float* g_all      = (const float*)d_in[13];
    const float* be_all     = (const float*)d_in[14];
    const float* W_msg      = (const float*)d_in[15];
    const float* b_msg      = (const float*)d_in[16];
    const float* g_conv     = (const float*)d_in[17];
    const float* be_conv    = (const float*)d_in[18];
    const float* W_o1       = (const float*)d_in[19];
    const float* b_o1       = (const float*)d_in[20];
    const float* W_o2       = (const float*)d_in[21];
    const float* b_o2       = (const float*)d_in[22];
    float* out = (float*)d_out;

    int N = in_sizes[0] / 6;
    int E = in_sizes[2] / 2;

    k_zero<<<1, 128>>>();
    k_enc_prep<<<592, 128>>>(x_cont, x_cat, datanorm, W_cont, b_cont,
                             emb_charge, emb_pdg, W_cat, b_cat, W_enc, b_enc,
                             g_all, be_all, W_msg, N);
    int NP = (E + 1) / 2;
    long long tot = (long long)NP * 8;
    int eb = (int)((tot + 255) / 256);
    k_edge<<<eb, 256>>>(edge_index, E, NP);
    k_agg_out<<<1184, 128>>>(g_all, be_all, b_msg, g_conv, be_conv,
                             W_o1, b_o1, W_o2, b_o2, out, N);
}